// round 5
// baseline (speedup 1.0000x reference)
#include <cuda_runtime.h>

// Depthwise 3x3 conv with one-hot (hard-softmax) weight == pure spatial shift:
//   out[b,c,h,w] = x[b,c,h+dh,w+dw]  (zero outside), (dh,dw) = abs-argmax of
// the 9 weights (first max wins, matching jnp.argmax).
// Shapes fixed: B=16, C=64, H=256, W=256 fp32.
//
// R4->R5: persistent grid (148*8 blocks, grid-stride over 1024-float4 tiles)
// to kill ~13 wave transitions; __ldcs (evict-first) loads since every byte
// is single-touch. Layout/MLP identical to the 76us R3/R4 kernel.

#define H_DIM 256
#define W_DIM 256
#define N4_TOTAL (16 * 64 * 256 * 64)   /* float4 units = 16,777,216 */
#define TILE4 1024                      /* float4 per block-tile */
#define N_TILES (N4_TOTAL / TILE4)      /* 16384 */

__device__ __forceinline__ float4
load_shifted(const float* __restrict__ x, int v, int dh, int dw) {
    // v = float4 output index. W=256 -> 64 float4/row.
    const int w4 = v & 63;
    const int h  = (v >> 6) & 255;
    const int bc = v >> 14;

    float4 val = make_float4(0.f, 0.f, 0.f, 0.f);
    const int hi = h + dh;
    if ((unsigned)hi < (unsigned)H_DIM) {
        const float* __restrict__ row = x + ((long long)bc * H_DIM + hi) * W_DIM;
        if (dw == 0) {
            val = __ldcs(reinterpret_cast<const float4*>(row) + w4);
        } else {
            const int wa = (w4 << 2) + dw;   // lane stride 16B -> coalesced
            val.x = ((unsigned)wa       < (unsigned)W_DIM) ? __ldcs(row + wa)     : 0.f;
            val.y = ((unsigned)(wa + 1) < (unsigned)W_DIM) ? __ldcs(row + wa + 1) : 0.f;
            val.z = ((unsigned)(wa + 2) < (unsigned)W_DIM) ? __ldcs(row + wa + 2) : 0.f;
            val.w = ((unsigned)(wa + 3) < (unsigned)W_DIM) ? __ldcs(row + wa + 3) : 0.f;
        }
    }
    return val;
}

__global__ void __launch_bounds__(256)
shift_persist_kernel(const float* __restrict__ x, const float* __restrict__ wt,
                     float* __restrict__ out) {
    __shared__ int s_dh, s_dw;
    if (threadIdx.x == 0) {
        float best = -1.0f;
        int bi = 0;
#pragma unroll
        for (int i = 0; i < 9; ++i) {
            float a = fabsf(__ldg(wt + i));
            if (a > best) { best = a; bi = i; }  // strict > : first max wins
        }
        s_dh = bi / 3 - 1;
        s_dw = bi % 3 - 1;
    }
    __syncthreads();
    const int dh = s_dh;
    const int dw = s_dw;

    float4* __restrict__ o4 = reinterpret_cast<float4*>(out);

    for (int tile = blockIdx.x; tile < N_TILES; tile += gridDim.x) {
        const int base = tile * TILE4;
        const int v0 = base + threadIdx.x;
        const int v1 = v0 + 256;
        const int v2 = v0 + 512;
        const int v3 = v0 + 768;

        // Four independent coalesced load chains (front-batched -> MLP 4).
        float4 a = load_shifted(x, v0, dh, dw);
        float4 b = load_shifted(x, v1, dh, dw);
        float4 c = load_shifted(x, v2, dh, dw);
        float4 d = load_shifted(x, v3, dh, dw);

        __stcs(o4 + v0, a);
        __stcs(o4 + v1, b);
        __stcs(o4 + v2, c);
        __stcs(o4 + v3, d);
    }
}

extern "C" void kernel_launch(void* const* d_in, const int* in_sizes, int n_in,
                              void* d_out, int out_size) {
    const float* x  = (const float*)d_in[0];
    const float* wt = (const float*)d_in[1];
    float* out = (float*)d_out;

    // Persistent: 8 blocks per SM on 148+ SMs (GB300 has 152).
    const int blocks = 148 * 8;  // 1184
    shift_persist_kernel<<<blocks, 256>>>(x, wt, out);
}

// round 6
// speedup vs baseline: 1.0879x; 1.0879x over previous
#include <cuda_runtime.h>

// Depthwise 3x3 conv with one-hot (hard-softmax) weight == pure spatial shift:
//   out[b,c,h,w] = x[b,c,h+dh,w+dw]  (zero outside), (dh,dw) = abs-argmax of
// the 9 weights (first max wins, matching jnp.argmax).
// Shapes fixed: B=16, C=64, H=256, W=256 fp32.
//
// R6: R3's proven layout (non-persistent, 2 warp-interleaved float4/thread),
// but the dw=+-1 path now uses ONE aligned LDG.128 per lane + warp shuffle to
// assemble the shifted vector (edge lane: 1 guarded scalar load), instead of
// 4x LDG.32. Cuts L1tex wavefronts ~4x on the shifted path.
//
// Warp-uniformity: each warp covers 32 aligned consecutive float4 = half a
// row, so h (and hi) are uniform per warp -> shuffles inside the hi-guard are
// warp-synchronous and safe. Grid covers n4 exactly (no partial warps).

#define H_DIM 256
#define W_DIM 256

__device__ __forceinline__ float4
load_shifted(const float* __restrict__ x, int v, int dh, int dw, int lane) {
    // v = float4 output index. W=256 -> 64 float4/row.
    const int w4 = v & 63;
    const int h  = (v >> 6) & 255;
    const int bc = v >> 14;

    float4 val = make_float4(0.f, 0.f, 0.f, 0.f);
    const int hi = h + dh;                 // warp-uniform
    if ((unsigned)hi < (unsigned)H_DIM) {
        const float* __restrict__ row = x + ((long long)bc * H_DIM + hi) * W_DIM;
        const float4 f = __ldg(reinterpret_cast<const float4*>(row) + w4);
        if (dw == 0) {
            val = f;
        } else if (dw == 1) {
            // need cols 4*w4+1 .. 4*w4+4  -> (f.y, f.z, f.w, next.x)
            float nx = __shfl_down_sync(0xffffffffu, f.x, 1);
            if (lane == 31)
                nx = (w4 == 63) ? 0.f : __ldg(row + (w4 << 2) + 4);
            val = make_float4(f.y, f.z, f.w, nx);
        } else {  // dw == -1
            // need cols 4*w4-1 .. 4*w4+2  -> (prev.w, f.x, f.y, f.z)
            float pw = __shfl_up_sync(0xffffffffu, f.w, 1);
            if (lane == 0)
                pw = (w4 == 0) ? 0.f : __ldg(row + (w4 << 2) - 1);
            val = make_float4(pw, f.x, f.y, f.z);
        }
    }
    return val;
}

__global__ void __launch_bounds__(256)
shift_shfl_kernel(const float* __restrict__ x, const float* __restrict__ wt,
                  float* __restrict__ out) {
    __shared__ int s_dh, s_dw;
    if (threadIdx.x == 0) {
        float best = -1.0f;
        int bi = 0;
#pragma unroll
        for (int i = 0; i < 9; ++i) {
            float a = fabsf(__ldg(wt + i));
            if (a > best) { best = a; bi = i; }  // strict > : first max wins
        }
        s_dh = bi / 3 - 1;
        s_dw = bi % 3 - 1;
    }
    __syncthreads();
    const int dh = s_dh;
    const int dw = s_dw;
    const int lane = threadIdx.x & 31;

    // Block covers 512 consecutive float4s; thread t handles t and t+256.
    const int base = blockIdx.x * 512;
    const int v0 = base + threadIdx.x;
    const int v1 = v0 + 256;

    float4 a = load_shifted(x, v0, dh, dw, lane);
    float4 b = load_shifted(x, v1, dh, dw, lane);

    float4* __restrict__ o4 = reinterpret_cast<float4*>(out);
    __stcs(o4 + v0, a);
    __stcs(o4 + v1, b);
}

extern "C" void kernel_launch(void* const* d_in, const int* in_sizes, int n_in,
                              void* d_out, int out_size) {
    const float* x  = (const float*)d_in[0];
    const float* wt = (const float*)d_in[1];
    float* out = (float*)d_out;

    const int n4 = out_size >> 2;   // 16,777,216 float4
    const int blocks = n4 / 512;    // 32768 blocks, 256 threads, 2 f4/thread
    shift_shfl_kernel<<<blocks, 256>>>(x, wt, out);
}